// round 1
// baseline (speedup 1.0000x reference)
#include <cuda_runtime.h>

// ---------------- problem constants ----------------
#define Bb   2
#define Ss   2048
#define DMm  256
#define DIi  512
#define NN   16
#define RR   32
#define MM   (Bb*Ss)          // 4096 rows
#define CHUNK 32
#define NCH  (Ss/CHUNK)       // 64 chunks per sequence

// ---------------- device scratch (no allocations allowed) ----------------
__device__ float g_res [MM*DMm];
__device__ float g_fwd [MM*DMm];
__device__ float g_xn  [MM*DMm];
__device__ float g_xs  [MM*DIi];
__device__ float g_z   [MM*DIi];
__device__ float g_xc  [MM*DIi];
__device__ float g_proj[MM*64];          // [xd(32) | B(16) | C(16)]
__device__ float g_delta[MM*DIi];
__device__ float g_yg  [MM*DIi];
__device__ float g_P   [Bb*NCH*DIi*NN];
__device__ float g_Q   [Bb*NCH*DIi*NN];
__device__ float g_Hin [Bb*NCH*DIi*NN];

__device__ __forceinline__ float siluf(float x){ return x / (1.f + __expf(-x)); }

// ---------------- init / copy ----------------
__global__ void k_init(const float* __restrict__ x, int rev){
  int idx = blockIdx.x*256 + threadIdx.x;       // MM*64 float4s
  int col = idx & 63;
  int m   = idx >> 6;
  int b = m >> 11, s = m & (Ss-1);
  int ms = rev ? (b*Ss + (Ss-1-s)) : m;
  reinterpret_cast<float4*>(g_res)[m*64+col] =
      reinterpret_cast<const float4*>(x)[ms*64+col];
}

__global__ void k_copy(){
  int idx = blockIdx.x*256 + threadIdx.x;
  reinterpret_cast<float4*>(g_fwd)[idx] = reinterpret_cast<const float4*>(g_res)[idx];
}

// ---------------- layernorm (1 warp per row of 256) ----------------
__global__ void k_ln(const float* __restrict__ g, const float* __restrict__ bt){
  int warp = (blockIdx.x*256 + threadIdx.x) >> 5;
  int lane = threadIdx.x & 31;
  const float* row = g_res + warp*DMm;
  float4 v0 = reinterpret_cast<const float4*>(row)[lane];
  float4 v1 = reinterpret_cast<const float4*>(row)[lane+32];
  float s = v0.x+v0.y+v0.z+v0.w + v1.x+v1.y+v1.z+v1.w;
  float q = v0.x*v0.x+v0.y*v0.y+v0.z*v0.z+v0.w*v0.w
          + v1.x*v1.x+v1.y*v1.y+v1.z*v1.z+v1.w*v1.w;
  #pragma unroll
  for (int o=16;o;o>>=1){ s += __shfl_xor_sync(~0u,s,o); q += __shfl_xor_sync(~0u,q,o); }
  float mean = s*(1.f/DMm);
  float var  = q*(1.f/DMm) - mean*mean;
  float r = rsqrtf(var + 1e-5f);
  float* orow = g_xn + warp*DMm;
  int c0 = lane*4, c1 = 128 + lane*4;
  float4 o0, o1;
  o0.x=(v0.x-mean)*r*g[c0+0]+bt[c0+0]; o0.y=(v0.y-mean)*r*g[c0+1]+bt[c0+1];
  o0.z=(v0.z-mean)*r*g[c0+2]+bt[c0+2]; o0.w=(v0.w-mean)*r*g[c0+3]+bt[c0+3];
  o1.x=(v1.x-mean)*r*g[c1+0]+bt[c1+0]; o1.y=(v1.y-mean)*r*g[c1+1]+bt[c1+1];
  o1.z=(v1.z-mean)*r*g[c1+2]+bt[c1+2]; o1.w=(v1.w-mean)*r*g[c1+3]+bt[c1+3];
  reinterpret_cast<float4*>(orow)[lane]    = o0;
  reinterpret_cast<float4*>(orow)[lane+32] = o1;
}

// ---------------- SGEMM core: 128x64 tile, 8x4 per thread, 256 threads ----------------
#define GEMM_PROLOGUE()                                            \
  __shared__ float As[16][128];                                    \
  __shared__ float Bs[16][64];                                     \
  int t = threadIdx.x;                                             \
  int tx = t & 15, ty = t >> 4;                                    \
  int lr = t >> 1, lk = (t & 1) * 8;                               \
  int bk = t >> 4, bc = (t & 15) * 4;                              \
  float acc[8][4] = {};

#define GEMM_COMPUTE()                                             \
  __syncthreads();                                                 \
  _Pragma("unroll")                                                \
  for (int kk=0; kk<16; kk++){                                     \
    float a[8], bb[4];                                             \
    _Pragma("unroll") for (int i=0;i<8;i++) a[i]=As[kk][ty*8+i];   \
    _Pragma("unroll") for (int j=0;j<4;j++) bb[j]=Bs[kk][tx*4+j];  \
    _Pragma("unroll") for (int i=0;i<8;i++)                        \
      _Pragma("unroll") for (int j=0;j<4;j++)                      \
        acc[i][j] += a[i]*bb[j];                                   \
  }                                                                \
  __syncthreads();

#define GEMM_LOAD_A(Aptr, lda)                                     \
  { float4 a0 = *(const float4*)((Aptr) + (row0+lr)*(lda) + k0+lk);      \
    float4 a1 = *(const float4*)((Aptr) + (row0+lr)*(lda) + k0+lk+4);    \
    As[lk+0][lr]=a0.x; As[lk+1][lr]=a0.y; As[lk+2][lr]=a0.z; As[lk+3][lr]=a0.w; \
    As[lk+4][lr]=a1.x; As[lk+5][lr]=a1.y; As[lk+6][lr]=a1.z; As[lk+7][lr]=a1.w; }

// in_proj: xn[4096,256] @ in_w[256,1024] -> xs | z
__global__ void k_gemm_in(const float* __restrict__ W){
  int row0 = blockIdx.y*128, col0 = blockIdx.x*64;
  GEMM_PROLOGUE();
  for (int k0=0;k0<DMm;k0+=16){
    GEMM_LOAD_A(g_xn, DMm);
    *(float4*)&Bs[bk][bc] = *(const float4*)(W + (k0+bk)*(2*DIi) + col0 + bc);
    GEMM_COMPUTE();
  }
  int cbase = col0 + tx*4;
  #pragma unroll
  for (int i=0;i<8;i++){
    int m = row0 + ty*8 + i;
    float4 v = make_float4(acc[i][0],acc[i][1],acc[i][2],acc[i][3]);
    if (cbase < DIi) *(float4*)&g_xs[m*DIi + cbase] = v;
    else             *(float4*)&g_z [m*DIi + cbase - DIi] = v;
  }
}

// x-proj: xc[4096,512] @ [xd_w|xB_w|xC_w] -> proj[4096,64]
__global__ void k_gemm_x(const float* __restrict__ xdw,
                         const float* __restrict__ xbw,
                         const float* __restrict__ xcw){
  int row0 = blockIdx.y*128;
  GEMM_PROLOGUE();
  const float* src; int strd, off;
  if      (bc < 32){ src = xdw; strd = 32; off = bc;      }
  else if (bc < 48){ src = xbw; strd = 16; off = bc - 32; }
  else             { src = xcw; strd = 16; off = bc - 48; }
  for (int k0=0;k0<DIi;k0+=16){
    GEMM_LOAD_A(g_xc, DIi);
    *(float4*)&Bs[bk][bc] = *(const float4*)(src + (k0+bk)*strd + off);
    GEMM_COMPUTE();
  }
  int cbase = tx*4;
  #pragma unroll
  for (int i=0;i<8;i++){
    int m = row0 + ty*8 + i;
    *(float4*)&g_proj[m*64 + cbase] =
        make_float4(acc[i][0],acc[i][1],acc[i][2],acc[i][3]);
  }
}

// out_proj: yg[4096,512] @ out_w[512,256] + residual -> res
__global__ void k_gemm_out(const float* __restrict__ W){
  int row0 = blockIdx.y*128, col0 = blockIdx.x*64;
  GEMM_PROLOGUE();
  for (int k0=0;k0<DIi;k0+=16){
    GEMM_LOAD_A(g_yg, DIi);
    *(float4*)&Bs[bk][bc] = *(const float4*)(W + (k0+bk)*DMm + col0 + bc);
    GEMM_COMPUTE();
  }
  int cbase = col0 + tx*4;
  #pragma unroll
  for (int i=0;i<8;i++){
    int m = row0 + ty*8 + i;
    float4 old = *(const float4*)&g_res[m*DMm + cbase];
    *(float4*)&g_res[m*DMm + cbase] =
        make_float4(acc[i][0]+old.x, acc[i][1]+old.y,
                    acc[i][2]+old.z, acc[i][3]+old.w);
  }
}

// merge: concat(fwd, bwd_reversed)[4096,512] @ merge_w[512,256] -> out
__global__ void k_merge(const float* __restrict__ W, float* __restrict__ out){
  int row0 = blockIdx.y*128, col0 = blockIdx.x*64;
  GEMM_PROLOGUE();
  int r = row0 + lr;
  int b = r >> 11, s = r & (Ss-1);
  int rrev = b*Ss + (Ss-1-s);
  for (int k0=0;k0<2*DMm;k0+=16){
    int kb = k0 + lk;
    const float* pa = (kb < DMm) ? (g_fwd + r*DMm + kb)
                                 : (g_res + rrev*DMm + (kb - DMm));
    float4 a0 = *(const float4*)pa;
    float4 a1 = *(const float4*)(pa+4);
    As[lk+0][lr]=a0.x; As[lk+1][lr]=a0.y; As[lk+2][lr]=a0.z; As[lk+3][lr]=a0.w;
    As[lk+4][lr]=a1.x; As[lk+5][lr]=a1.y; As[lk+6][lr]=a1.z; As[lk+7][lr]=a1.w;
    *(float4*)&Bs[bk][bc] = *(const float4*)(W + (k0+bk)*DMm + col0 + bc);
    GEMM_COMPUTE();
  }
  int cbase = col0 + tx*4;
  #pragma unroll
  for (int i=0;i<8;i++){
    int m = row0 + ty*8 + i;
    *(float4*)&out[m*DMm + cbase] =
        make_float4(acc[i][0],acc[i][1],acc[i][2],acc[i][3]);
  }
}

// ---------------- causal depthwise conv (K=4) + silu ----------------
__global__ void k_conv(const float* __restrict__ cw, const float* __restrict__ cb){
  int idx = blockIdx.x*256 + threadIdx.x;   // MM*128
  int d4 = idx & 127, m = idx >> 7;
  int s = m & (Ss-1);
  int d = d4*4;
  float4 w0 = *(const float4*)(cw + (d+0)*4);
  float4 w1 = *(const float4*)(cw + (d+1)*4);
  float4 w2 = *(const float4*)(cw + (d+2)*4);
  float4 w3 = *(const float4*)(cw + (d+3)*4);
  const float* wp0=(const float*)&w0; const float* wp1=(const float*)&w1;
  const float* wp2=(const float*)&w2; const float* wp3=(const float*)&w3;
  float4 acc = *(const float4*)(cb + d);
  #pragma unroll
  for (int k=0;k<4;k++){
    int sp = s-3+k;
    if (sp >= 0){
      float4 xv = *(const float4*)(g_xs + (m-3+k)*DIi + d);
      acc.x += xv.x * wp0[k];
      acc.y += xv.y * wp1[k];
      acc.z += xv.z * wp2[k];
      acc.w += xv.w * wp3[k];
    }
  }
  acc.x = siluf(acc.x); acc.y = siluf(acc.y);
  acc.z = siluf(acc.z); acc.w = siluf(acc.w);
  *(float4*)&g_xc[m*DIi + d] = acc;
}

// ---------------- delta = softplus(proj[:, :32] @ dtp_w + dtp_b) ----------------
__global__ void k_delta(const float* __restrict__ dtpw, const float* __restrict__ dtpb){
  __shared__ float pr[RR];
  int m = blockIdx.x;
  int d = threadIdx.x;
  if (d < RR) pr[d] = g_proj[m*64 + d];
  __syncthreads();
  float a = dtpb[d];
  #pragma unroll
  for (int r=0;r<RR;r++) a += pr[r]*dtpw[r*DIi + d];
  float sp = (a > 20.f) ? a : log1pf(__expf(a));
  g_delta[m*DIi + d] = sp;
}

// ---------------- chunked scan: phase 1 (per-chunk P, Q with h0=0) ----------------
__global__ void k_scan1(const float* __restrict__ Alog){
  __shared__ float sB[CHUNK][NN];
  int bc = blockIdx.x;                // b*NCH + c
  int b = bc / NCH, c = bc % NCH;
  int d = threadIdx.x;
  int m0 = b*Ss + c*CHUNK;
  { int s = d >> 4, n = d & 15; sB[s][n] = g_proj[(m0+s)*64 + 32 + n]; }
  float A[NN];
  #pragma unroll
  for (int n=0;n<NN;n++) A[n] = -expf(Alog[d*NN + n]);
  __syncthreads();
  float h[NN], P[NN];
  #pragma unroll
  for (int n=0;n<NN;n++){ h[n]=0.f; P[n]=1.f; }
  for (int s=0;s<CHUNK;s++){
    int m = m0 + s;
    float dlt = g_delta[m*DIi + d];
    float dx  = dlt * g_xc[m*DIi + d];
    #pragma unroll
    for (int n=0;n<NN;n++){
      float dA = __expf(dlt*A[n]);
      h[n] = dA*h[n] + dx*sB[s][n];
      P[n] *= dA;
    }
  }
  int base = (bc*DIi + d)*NN;
  #pragma unroll
  for (int n=0;n<NN;n++){ g_Q[base+n]=h[n]; g_P[base+n]=P[n]; }
}

// ---------------- phase 2: sequential combine across chunks ----------------
__global__ void k_comb(){
  int i = blockIdx.x*256 + threadIdx.x;     // Bb*DIi*NN = 16384
  int n = i & 15, d = (i >> 4) & (DIi-1), b = i >> 13;
  float H = 0.f;
  for (int c=0;c<NCH;c++){
    int idx = ((b*NCH+c)*DIi + d)*NN + n;
    g_Hin[idx] = H;
    H = g_P[idx]*H + g_Q[idx];
  }
}

// ---------------- phase 3: replay with correct carry, produce gated y ----------------
__global__ void k_scan2(const float* __restrict__ Alog, const float* __restrict__ Dp){
  __shared__ float sB[CHUNK][NN];
  __shared__ float sC[CHUNK][NN];
  int bc = blockIdx.x;
  int b = bc / NCH, c = bc % NCH;
  int d = threadIdx.x;
  int m0 = b*Ss + c*CHUNK;
  { int s = d >> 4, n = d & 15;
    sB[s][n] = g_proj[(m0+s)*64 + 32 + n];
    sC[s][n] = g_proj[(m0+s)*64 + 48 + n]; }
  float A[NN];
  #pragma unroll
  for (int n=0;n<NN;n++) A[n] = -expf(Alog[d*NN + n]);
  float h[NN];
  int base = (bc*DIi + d)*NN;
  #pragma unroll
  for (int n=0;n<NN;n++) h[n] = g_Hin[base+n];
  float Dv = Dp[d];
  __syncthreads();
  for (int s=0;s<CHUNK;s++){
    int m = m0 + s;
    float dlt = g_delta[m*DIi + d];
    float x   = g_xc[m*DIi + d];
    float dx  = dlt * x;
    float y = 0.f;
    #pragma unroll
    for (int n=0;n<NN;n++){
      float dA = __expf(dlt*A[n]);
      h[n] = dA*h[n] + dx*sB[s][n];
      y += h[n]*sC[s][n];
    }
    y += Dv*x;
    float zv = g_z[m*DIi + d];
    g_yg[m*DIi + d] = y * siluf(zv);
  }
}

// ---------------- driver ----------------
extern "C" void kernel_launch(void* const* d_in, const int* in_sizes, int n_in,
                              void* d_out, int out_size){
  const float* x      = (const float*)d_in[0];
  const float* in_w   = (const float*)d_in[1];
  const float* conv_w = (const float*)d_in[2];
  const float* conv_b = (const float*)d_in[3];
  const float* A_log  = (const float*)d_in[4];
  const float* xd_w   = (const float*)d_in[5];
  const float* xB_w   = (const float*)d_in[6];
  const float* xC_w   = (const float*)d_in[7];
  const float* dtp_w  = (const float*)d_in[8];
  const float* dtp_b  = (const float*)d_in[9];
  const float* Dp     = (const float*)d_in[10];
  const float* out_w  = (const float*)d_in[11];
  const float* ln_g   = (const float*)d_in[12];
  const float* ln_b   = (const float*)d_in[13];
  const float* merge_w= (const float*)d_in[14];
  float* out = (float*)d_out;

  for (int chain=0; chain<2; chain++){
    k_init<<<MM*64/256, 256>>>(x, chain);
    for (int bi=0; bi<2; bi++){
      int blk = chain*2 + bi;
      k_ln      <<<MM/8, 256>>>(ln_g + blk*DMm, ln_b + blk*DMm);
      k_gemm_in <<<dim3(16,32), 256>>>(in_w + (size_t)blk*DMm*2*DIi);
      k_conv    <<<MM*128/256, 256>>>(conv_w + blk*DIi*4, conv_b + blk*DIi);
      k_gemm_x  <<<dim3(1,32), 256>>>(xd_w + blk*DIi*RR,
                                      xB_w + blk*DIi*NN,
                                      xC_w + blk*DIi*NN);
      k_delta   <<<MM, DIi>>>(dtp_w + blk*RR*DIi, dtp_b + blk*DIi);
      k_scan1   <<<Bb*NCH, DIi>>>(A_log + blk*DIi*NN);
      k_comb    <<<64, 256>>>();
      k_scan2   <<<Bb*NCH, DIi>>>(A_log + blk*DIi*NN, Dp + blk*DIi);
      k_gemm_out<<<dim3(4,32), 256>>>(out_w + blk*DIi*DMm);
    }
    if (chain == 0) k_copy<<<MM*64/256, 256>>>();
  }
  k_merge<<<dim3(4,32), 256>>>(merge_w, out);
}